// round 5
// baseline (speedup 1.0000x reference)
#include <cuda_runtime.h>
#include <math.h>
#include <stdint.h>

#define IN_CH   512
#define NHEADS  8
#define H1DIM   64
#define OUT_CH  128
#define NMAX    50000
#define EMAX    800000
#define ETOT    (EMAX + NMAX)

// ------------------ scratch (static device globals; no allocs) ---------------
__device__ float g_h1   [NMAX * H1DIM];
__device__ float g_s1   [NMAX * NHEADS];
__device__ float g_d1   [NMAX * NHEADS];
__device__ float g_h1b  [NMAX * H1DIM];
__device__ float g_h2   [NMAX * OUT_CH];
__device__ float g_s2   [NMAX];
__device__ float g_d2   [NMAX];
__device__ int   g_deg   [NMAX];
__device__ int   g_rowptr[NMAX + 1];
__device__ int   g_cur   [NMAX];
__device__ int   g_csrc  [ETOT];
__device__ float g_WT1  [IN_CH * H1DIM];    // W1^T  [64][512]
__device__ float g_WT2  [H1DIM * OUT_CH];   // W2^T  [128][64]

// ------------------ tf32 helpers ---------------------------------------------
__device__ __forceinline__ unsigned f2tf(float x)
{
    unsigned u;
    asm("cvt.rna.tf32.f32 %0, %1;" : "=r"(u) : "f"(x));
    return u;
}

__device__ __forceinline__ void split_tf(uint32_t raw, uint32_t& hi, uint32_t& lo)
{
    float x = __uint_as_float(raw);
    unsigned h = f2tf(x);
    hi = h;
    lo = f2tf(x - __uint_as_float(h));
}

__device__ __forceinline__ void mma_tf32(float* c, const uint32_t* a, const uint32_t* b)
{
    asm volatile(
        "mma.sync.aligned.m16n8k8.row.col.f32.tf32.tf32.f32 "
        "{%0,%1,%2,%3}, {%4,%5,%6,%7}, {%8,%9}, {%0,%1,%2,%3};\n"
        : "+f"(c[0]), "+f"(c[1]), "+f"(c[2]), "+f"(c[3])
        : "r"(a[0]), "r"(a[1]), "r"(a[2]), "r"(a[3]), "r"(b[0]), "r"(b[1]));
}

__device__ __forceinline__ void ldsm4(uint32_t* r, uint32_t addr)
{
    asm volatile("ldmatrix.sync.aligned.m8n8.x4.shared.b16 {%0,%1,%2,%3}, [%4];"
        : "=r"(r[0]), "=r"(r[1]), "=r"(r[2]), "=r"(r[3]) : "r"(addr));
}

__device__ __forceinline__ void cpa16(uint32_t dst, const void* src, int sz)
{
    asm volatile("cp.async.cg.shared.global [%0], [%1], 16, %2;\n"
        :: "r"(dst), "l"(src), "r"(sz));
}

// ------------------ tensor-core 3xTF32 GEMM, ldmatrix + cp.async -------------
// C[M,N] = A[M,K] @ BT[N,K]^T ; K % 32 == 0, N % 64 == 0.
#define GBM 128
#define GBN 64
#define GBK 32
#define KQT 8                    // 4-wide k-quads per tile

__global__ void __launch_bounds__(256)
gemm_tf32_v2(const float* __restrict__ A, const float* __restrict__ BT,
             float* __restrict__ C, int M, int N, int K)
{
    __shared__ float4 AS[2][KQT * GBM];   // [stage][q*128 + (m^q)]
    __shared__ float4 BS[2][KQT * GBN];   // [stage][q*64  + (n^q)]

    int tid  = threadIdx.x;
    int w    = tid >> 5, lane = tid & 31;
    int wm   = (w & 3) << 5;
    int wn   = (w >> 2) << 5;
    int m0   = blockIdx.x * GBM;
    int n0   = blockIdx.y * GBN;

    uint32_t asbase = (uint32_t)__cvta_generic_to_shared(&AS[0][0]);
    uint32_t bsbase = (uint32_t)__cvta_generic_to_shared(&BS[0][0]);

    float acc[2][4][4];
#pragma unroll
    for (int i = 0; i < 2; i++)
#pragma unroll
        for (int j = 0; j < 4; j++)
#pragma unroll
            for (int r = 0; r < 4; r++) acc[i][j][r] = 0.f;

    const int T = K / GBK;

    auto load_tile = [&](int kt, int st) {
        int k0 = kt * GBK;
        // A tile: 128 rows x 8 quads (1024 x 16B)
#pragma unroll
        for (int i = 0; i < 4; i++) {
            int id = tid + 256 * i;
            int q  = id & 7, r = id >> 3;
            int gr = m0 + r;
            const float* src = A + (size_t)gr * K + k0 + q * 4;
            int sz = (gr < M) ? 16 : 0;
            uint32_t dst = asbase + (uint32_t)(st * (KQT * GBM) + q * GBM + (r ^ q)) * 16u;
            cpa16(dst, src, sz);
        }
        // B tile: 64 n x 8 quads (512 x 16B), from transposed weights
#pragma unroll
        for (int i = 0; i < 2; i++) {
            int id = tid + 256 * i;
            int q  = id & 7, n = id >> 3;
            const float* src = BT + (size_t)(n0 + n) * K + k0 + q * 4;
            uint32_t dst = bsbase + (uint32_t)(st * (KQT * GBN) + q * GBN + (n ^ q)) * 16u;
            cpa16(dst, src, 16);
        }
    };

    load_tile(0, 0);
    asm volatile("cp.async.commit_group;\n");

    for (int kt = 0; kt < T; kt++) {
        if (kt + 1 < T) load_tile(kt + 1, (kt + 1) & 1);
        asm volatile("cp.async.commit_group;\n");
        asm volatile("cp.async.wait_group 1;\n");
        __syncthreads();

        uint32_t sA = asbase + (uint32_t)((kt & 1) * (KQT * GBM)) * 16u;
        uint32_t sB = bsbase + (uint32_t)((kt & 1) * (KQT * GBN)) * 16u;

#pragma unroll
        for (int ks = 0; ks < GBK; ks += 8) {
            int kq = ks >> 2;
            uint32_t araw[2][4], braw[2][4];
            // A fragments (raw fp32): matrices (m8 blk, kq) / (m8+8, kq) / (.., kq+1)
#pragma unroll
            for (int i = 0; i < 2; i++) {
                int j2  = lane >> 3;
                int kqs = kq + (j2 >> 1);
                int mr  = wm + i * 16 + (lane & 7) + ((j2 & 1) << 3);
                ldsm4(araw[i], sA + (uint32_t)(kqs * GBM + (mr ^ kqs)) * 16u);
            }
            // B fragments: x4 covers n-blocks {2i, 2i+1} x {kq, kq+1}
#pragma unroll
            for (int i = 0; i < 2; i++) {
                int pair = lane >> 3;
                int kqs  = kq + (pair & 1);
                int nr   = wn + i * 16 + ((pair >> 1) << 3) + (lane & 7);
                ldsm4(braw[i], sB + (uint32_t)(kqs * GBN + (nr ^ kqs)) * 16u);
            }
            // split raw -> tf32 hi/lo in registers
            uint32_t ah[2][4], al[2][4], bh[4][2], bl[4][2];
#pragma unroll
            for (int i = 0; i < 2; i++)
#pragma unroll
                for (int r = 0; r < 4; r++) split_tf(araw[i][r], ah[i][r], al[i][r]);
#pragma unroll
            for (int i = 0; i < 2; i++) {
                split_tf(braw[i][0], bh[2 * i    ][0], bl[2 * i    ][0]);
                split_tf(braw[i][1], bh[2 * i    ][1], bl[2 * i    ][1]);
                split_tf(braw[i][2], bh[2 * i + 1][0], bl[2 * i + 1][0]);
                split_tf(braw[i][3], bh[2 * i + 1][1], bl[2 * i + 1][1]);
            }
            // 3-term product
#pragma unroll
            for (int i = 0; i < 2; i++)
#pragma unroll
                for (int j = 0; j < 4; j++) {
                    mma_tf32(acc[i][j], ah[i], bh[j]);
                    mma_tf32(acc[i][j], al[i], bh[j]);
                    mma_tf32(acc[i][j], ah[i], bl[j]);
                }
        }
        __syncthreads();
    }

    // epilogue
    int g = lane >> 2, tig = lane & 3;
#pragma unroll
    for (int i = 0; i < 2; i++) {
#pragma unroll
        for (int j = 0; j < 4; j++) {
            int row = m0 + wm + i * 16 + g;
            int col = n0 + wn + j * 8 + 2 * tig;
            if (row < M)
                *(float2*)(C + (size_t)row * N + col) =
                    make_float2(acc[i][j][0], acc[i][j][1]);
            if (row + 8 < M)
                *(float2*)(C + (size_t)(row + 8) * N + col) =
                    make_float2(acc[i][j][2], acc[i][j][3]);
        }
    }
}

// ------------------ weight transpose -----------------------------------------
__global__ void transpose_w(const float* __restrict__ W, float* __restrict__ WT,
                            int K, int N)
{
    int i = blockIdx.x * blockDim.x + threadIdx.x;
    if (i >= K * N) return;
    int k = i / N, n = i % N;
    WT[n * K + k] = W[i];
}

// ------------------ CSR build ------------------------------------------------
__global__ void count_kernel(const int* __restrict__ dst, int ne, int n)
{
    int i = blockIdx.x * blockDim.x + threadIdx.x;
    if (i >= ne + n) return;
    int d = (i < ne) ? dst[i] : (i - ne);
    atomicAdd(&g_deg[d], 1);
}

__global__ void __launch_bounds__(1024) scan_kernel(int n)
{
    __shared__ int warpsums[32];
    __shared__ int s_carry;
    int tid = threadIdx.x, lane = tid & 31, wid = tid >> 5;
    if (tid == 0) s_carry = 0;
    __syncthreads();

    for (int base = 0; base < n; base += 4096) {
        int i0 = base + tid * 4;
        int v[4];
#pragma unroll
        for (int k = 0; k < 4; k++) {
            int i = i0 + k;
            v[k] = (i < n) ? g_deg[i] : 0;
        }
        int tsum = v[0] + v[1] + v[2] + v[3];
        int x = tsum;
#pragma unroll
        for (int off = 1; off < 32; off <<= 1) {
            int t = __shfl_up_sync(0xffffffffu, x, off);
            if (lane >= off) x += t;
        }
        if (lane == 31) warpsums[wid] = x;
        __syncthreads();
        if (wid == 0) {
            int wv = warpsums[lane];
#pragma unroll
            for (int off = 1; off < 32; off <<= 1) {
                int t = __shfl_up_sync(0xffffffffu, wv, off);
                if (lane >= off) wv += t;
            }
            warpsums[lane] = wv;
        }
        __syncthreads();
        int warp_off = (wid > 0) ? warpsums[wid - 1] : 0;
        int run = s_carry + warp_off + (x - tsum);
#pragma unroll
        for (int k = 0; k < 4; k++) {
            int i = i0 + k;
            if (i < n) { g_rowptr[i] = run; g_cur[i] = run; }
            run += v[k];
        }
        __syncthreads();
        if (tid == 0) s_carry += warpsums[31];
        __syncthreads();
    }
    if (threadIdx.x == 0) g_rowptr[n] = s_carry;
}

__global__ void scatter_kernel(const int* __restrict__ src,
                               const int* __restrict__ dst, int ne, int n)
{
    int i = blockIdx.x * blockDim.x + threadIdx.x;
    if (i >= ne + n) return;
    int s, d;
    if (i < ne) { s = src[i]; d = dst[i]; }
    else        { s = d = i - ne; }
    int pos = atomicAdd(&g_cur[d], 1);
    g_csrc[pos] = s;
}

// ------------------ layer-1 per-node attention coefficients ------------------
__global__ void sd1_kernel(const float* __restrict__ att_src,
                           const float* __restrict__ att_dst, int n)
{
    int i = blockIdx.x * blockDim.x + threadIdx.x;
    if (i >= n * NHEADS) return;
    int node = i >> 3, h = i & 7;
    const float* hp = g_h1 + node * H1DIM + h * 8;
    float s = 0.f, d = 0.f;
#pragma unroll
    for (int c = 0; c < 8; c++) {
        float v = hp[c];
        s = fmaf(v, att_src[h * 8 + c], s);
        d = fmaf(v, att_dst[h * 8 + c], d);
    }
    g_s1[i] = s;
    g_d1[i] = d;
}

// ------------------ layer-1 gather (4-wide unrolled) -------------------------
__global__ void __launch_bounds__(256) gather1_kernel(const float* __restrict__ bias, int n)
{
    int gw   = (blockIdx.x * blockDim.x + threadIdx.x) >> 5;
    int lane = threadIdx.x & 31;
    if (gw >= n) return;
    int h = lane >> 2;
    float dv = g_d1[gw * NHEADS + h];
    int j0 = g_rowptr[gw], j1 = g_rowptr[gw + 1];
    float acc0 = 0.f, acc1 = 0.f, den = 0.f;
    int j = j0;
    for (; j + 3 < j1; j += 4) {
        int s0 = g_csrc[j], s1 = g_csrc[j + 1], s2 = g_csrc[j + 2], s3 = g_csrc[j + 3];
        float a0 = g_s1[s0 * NHEADS + h] + dv;
        float a1 = g_s1[s1 * NHEADS + h] + dv;
        float a2 = g_s1[s2 * NHEADS + h] + dv;
        float a3 = g_s1[s3 * NHEADS + h] + dv;
        float2 h0 = *(const float2*)(g_h1 + s0 * H1DIM + lane * 2);
        float2 h1 = *(const float2*)(g_h1 + s1 * H1DIM + lane * 2);
        float2 h2 = *(const float2*)(g_h1 + s2 * H1DIM + lane * 2);
        float2 h3 = *(const float2*)(g_h1 + s3 * H1DIM + lane * 2);
        a0 = (a0 > 0.f) ? a0 : 0.2f * a0;  float e0 = __expf(a0);
        a1 = (a1 > 0.f) ? a1 : 0.2f * a1;  float e1 = __expf(a1);
        a2 = (a2 > 0.f) ? a2 : 0.2f * a2;  float e2 = __expf(a2);
        a3 = (a3 > 0.f) ? a3 : 0.2f * a3;  float e3 = __expf(a3);
        den += (e0 + e1) + (e2 + e3);
        acc0 = fmaf(e0, h0.x, acc0); acc1 = fmaf(e0, h0.y, acc1);
        acc0 = fmaf(e1, h1.x, acc0); acc1 = fmaf(e1, h1.y, acc1);
        acc0 = fmaf(e2, h2.x, acc0); acc1 = fmaf(e2, h2.y, acc1);
        acc0 = fmaf(e3, h3.x, acc0); acc1 = fmaf(e3, h3.y, acc1);
    }
    for (; j < j1; j++) {
        int s = g_csrc[j];
        float a = g_s1[s * NHEADS + h] + dv;
        a = (a > 0.f) ? a : 0.2f * a;
        float ea = __expf(a);
        den += ea;
        float2 hv = *(const float2*)(g_h1 + s * H1DIM + lane * 2);
        acc0 = fmaf(ea, hv.x, acc0);
        acc1 = fmaf(ea, hv.y, acc1);
    }
    float inv = 1.f / den;
    int c = lane * 2;
    float v0 = acc0 * inv + bias[c];
    float v1 = acc1 * inv + bias[c + 1];
    v0 = (v0 > 0.f) ? v0 : expm1f(v0);
    v1 = (v1 > 0.f) ? v1 : expm1f(v1);
    *(float2*)(g_h1b + gw * H1DIM + c) = make_float2(v0, v1);
}

// ------------------ layer-2 per-node attention coefficients ------------------
__global__ void sd2_kernel(const float* __restrict__ att_src,
                           const float* __restrict__ att_dst, int n)
{
    int gt   = blockIdx.x * blockDim.x + threadIdx.x;
    int node = gt >> 5;
    int lane = gt & 31;
    if (node >= n) return;
    float4 hv = *(const float4*)(g_h2 + (size_t)node * OUT_CH + lane * 4);
    float4 as = *(const float4*)(att_src + lane * 4);
    float4 ad = *(const float4*)(att_dst + lane * 4);
    float s = hv.x * as.x + hv.y * as.y + hv.z * as.z + hv.w * as.w;
    float d = hv.x * ad.x + hv.y * ad.y + hv.z * ad.z + hv.w * ad.w;
#pragma unroll
    for (int off = 16; off > 0; off >>= 1) {
        s += __shfl_down_sync(0xffffffffu, s, off);
        d += __shfl_down_sync(0xffffffffu, d, off);
    }
    if (lane == 0) { g_s2[node] = s; g_d2[node] = d; }
}

// ------------------ layer-2 gather (4-wide unrolled) -> final output ---------
__global__ void __launch_bounds__(256) gather2_kernel(const float* __restrict__ bias,
                                                      float* __restrict__ out, int n)
{
    int gw   = (blockIdx.x * blockDim.x + threadIdx.x) >> 5;
    int lane = threadIdx.x & 31;
    if (gw >= n) return;
    float dv = g_d2[gw];
    int j0 = g_rowptr[gw], j1 = g_rowptr[gw + 1];
    float a0 = 0.f, a1 = 0.f, a2 = 0.f, a3 = 0.f, den = 0.f;
    int j = j0;
    for (; j + 3 < j1; j += 4) {
        int s0 = g_csrc[j], s1 = g_csrc[j + 1], s2 = g_csrc[j + 2], s3 = g_csrc[j + 3];
        float x0 = g_s2[s0] + dv, x1 = g_s2[s1] + dv;
        float x2 = g_s2[s2] + dv, x3 = g_s2[s3] + dv;
        float4 h0 = *(const float4*)(g_h2 + (size_t)s0 * OUT_CH + lane * 4);
        float4 h1 = *(const float4*)(g_h2 + (size_t)s1 * OUT_CH + lane * 4);
        float4 h2 = *(const float4*)(g_h2 + (size_t)s2 * OUT_CH + lane * 4);
        float4 h3 = *(const float4*)(g_h2 + (size_t)s3 * OUT_CH + lane * 4);
        x0 = (x0 > 0.f) ? x0 : 0.2f * x0;  float e0 = __expf(x0);
        x1 = (x1 > 0.f) ? x1 : 0.2f * x1;  float e1 = __expf(x1);
        x2 = (x2 > 0.f) ? x2 : 0.2f * x2;  float e2 = __expf(x2);
        x3 = (x3 > 0.f) ? x3 : 0.2f * x3;  float e3 = __expf(x3);
        den += (e0 + e1) + (e2 + e3);
        a0 = fmaf(e0, h0.x, a0); a1 = fmaf(e0, h0.y, a1);
        a2 = fmaf(e0, h0.z, a2); a3 = fmaf(e0, h0.w, a3);
        a0 = fmaf(e1, h1.x, a0); a1 = fmaf(e1, h1.y, a1);
        a2 = fmaf(e1, h1.z, a2); a3 = fmaf(e1, h1.w, a3);
        a0 = fmaf(e2, h2.x, a0); a1 = fmaf(e2, h2.y, a1);
        a2 = fmaf(e2, h2.z, a2); a3 = fmaf(e2, h2.w, a3);
        a0 = fmaf(e3, h3.x, a0); a1 = fmaf(e3, h3.y, a1);
        a2 = fmaf(e3, h3.z, a2); a3 = fmaf(e3, h3.w, a3);
    }
    for (; j < j1; j++) {
        int s = g_csrc[j];
        float x = g_s2[s] + dv;
        x = (x > 0.f) ? x : 0.2f * x;
        float ea = __expf(x);
        den += ea;
        float4 hv = *(const float4*)(g_h2 + (size_t)s * OUT_CH + lane * 4);
        a0 = fmaf(ea, hv.x, a0);
        a1 = fmaf(ea, hv.y, a1);
        a2 = fmaf(ea, hv.z, a2);
        a3 = fmaf(ea, hv.w, a3);
    }
    float inv = 1.f / den;
    int c = lane * 4;
    float v0 = a0 * inv + bias[c + 0];
    float v1 = a1 * inv + bias[c + 1];
    float v2 = a2 * inv + bias[c + 2];
    float v3 = a3 * inv + bias[c + 3];
    v0 = (v0 > 0.f) ? v0 : expm1f(v0);
    v1 = (v1 > 0.f) ? v1 : expm1f(v1);
    v2 = (v2 > 0.f) ? v2 : expm1f(v2);
    v3 = (v3 > 0.f) ? v3 : expm1f(v3);
    *(float4*)(out + (size_t)gw * OUT_CH + c) = make_float4(v0, v1, v2, v3);
}

// ------------------ launch ---------------------------------------------------
extern "C" void kernel_launch(void* const* d_in, const int* in_sizes, int n_in,
                              void* d_out, int out_size)
{
    const float* x   = (const float*)d_in[0];
    const int*   ei  = (const int*)  d_in[1];
    const float* W1  = (const float*)d_in[2];
    const float* as1 = (const float*)d_in[3];
    const float* ad1 = (const float*)d_in[4];
    const float* b1  = (const float*)d_in[5];
    const float* W2  = (const float*)d_in[6];
    const float* as2 = (const float*)d_in[7];
    const float* ad2 = (const float*)d_in[8];
    const float* b2  = (const float*)d_in[9];
    float* out = (float*)d_out;

    int n = in_sizes[0] / IN_CH;
    int e = in_sizes[1] / 2;
    const int* src = ei;
    const int* dst = ei + e;

    void *p_h1, *p_h1b, *p_h2, *p_wt1, *p_wt2, *p;
    cudaGetSymbolAddress(&p_h1,  g_h1);
    cudaGetSymbolAddress(&p_h1b, g_h1b);
    cudaGetSymbolAddress(&p_h2,  g_h2);
    cudaGetSymbolAddress(&p_wt1, g_WT1);
    cudaGetSymbolAddress(&p_wt2, g_WT2);

    // ---- weight transposes ----
    transpose_w<<<(IN_CH * H1DIM + 255) / 256, 256>>>(W1, (float*)p_wt1, IN_CH, H1DIM);
    transpose_w<<<(H1DIM * OUT_CH + 255) / 256, 256>>>(W2, (float*)p_wt2, H1DIM, OUT_CH);

    // ---- CSR build (shared by both layers) ----
    cudaGetSymbolAddress(&p, g_deg);
    cudaMemsetAsync(p, 0, (size_t)n * 4);
    count_kernel<<<(e + n + 255) / 256, 256>>>(dst, e, n);
    scan_kernel<<<1, 1024>>>(n);
    scatter_kernel<<<(e + n + 255) / 256, 256>>>(src, dst, e, n);

    // ---- layer 1 ----
    {
        dim3 grid((n + GBM - 1) / GBM, H1DIM / GBN);
        gemm_tf32_v2<<<grid, 256>>>(x, (const float*)p_wt1, (float*)p_h1, n, H1DIM, IN_CH);
    }
    sd1_kernel<<<(n * NHEADS + 255) / 256, 256>>>(as1, ad1, n);
    gather1_kernel<<<(n * 32 + 255) / 256, 256>>>(b1, n);

    // ---- layer 2 ----
    {
        dim3 grid((n + GBM - 1) / GBM, OUT_CH / GBN);
        gemm_tf32_v2<<<grid, 256>>>((const float*)p_h1b, (const float*)p_wt2, (float*)p_h2, n, OUT_CH, H1DIM);
    }
    sd2_kernel<<<(n * 32 + 255) / 256, 256>>>(as2, ad2, n);
    gather2_kernel<<<(n * 32 + 255) / 256, 256>>>(b2, out, n);
}

// round 6
// speedup vs baseline: 1.1947x; 1.1947x over previous
#include <cuda_runtime.h>
#include <math.h>
#include <stdint.h>

#define IN_CH   512
#define NHEADS  8
#define H1DIM   64
#define OUT_CH  128
#define NMAX    50000
#define EMAX    800000
#define ETOT    (EMAX + NMAX)

// ------------------ scratch (static device globals; no allocs) ---------------
__device__ float g_h1   [NMAX * H1DIM];
__device__ float g_s1   [NMAX * NHEADS];
__device__ float g_d1   [NMAX * NHEADS];
__device__ float g_h1b  [NMAX * H1DIM];
__device__ float g_h2   [NMAX * OUT_CH];
__device__ float g_s2   [NMAX];
__device__ float g_d2   [NMAX];
__device__ int   g_deg   [NMAX];
__device__ int   g_rowptr[NMAX + 1];
__device__ int   g_cur   [NMAX];
__device__ int   g_csrc  [ETOT];
__device__ int   g_blocksum[16];
__device__ int   g_blockoff[16];

// ------------------ 3xTF32 tensor-core GEMM (R4 v1) + fused attention dots ---
__device__ __forceinline__ unsigned f2tf(float x)
{
    unsigned u;
    asm("cvt.rna.tf32.f32 %0, %1;" : "=r"(u) : "f"(x));
    return u;
}

__device__ __forceinline__ void mma_tf32(float* c, const unsigned* a, const unsigned* b)
{
    asm volatile(
        "mma.sync.aligned.m16n8k8.row.col.f32.tf32.tf32.f32 "
        "{%0,%1,%2,%3}, {%4,%5,%6,%7}, {%8,%9}, {%0,%1,%2,%3};\n"
        : "+f"(c[0]), "+f"(c[1]), "+f"(c[2]), "+f"(c[3])
        : "r"(a[0]), "r"(a[1]), "r"(a[2]), "r"(a[3]), "r"(b[0]), "r"(b[1]));
}

#define GBM 128
#define GBN 64
#define GBK 16

// C[M,N] = A[M,K] @ B[K,N]; if fuse!=0 also writes per-head attention dots:
//   sout[row*NHEADS+h] = sum_c C[row, 8h+c]*asv[8h+c], same for dout/adv.
__global__ void __launch_bounds__(256)
gemm_tf32(const float* __restrict__ A, const float* __restrict__ B,
          float* __restrict__ C, int M, int N, int K,
          const float* __restrict__ asv, const float* __restrict__ adv,
          float* __restrict__ sout, float* __restrict__ dout, int fuse)
{
    __shared__ float Ah[GBK][GBM + 8], Al[GBK][GBM + 8];
    __shared__ float Bh[GBK][GBN + 8], Bl[GBK][GBN + 8];

    int tid  = threadIdx.x;
    int w    = tid >> 5, lane = tid & 31;
    int g    = lane >> 2, tig = lane & 3;
    int wm   = (w & 3) * 32;
    int wn   = (w >> 2) * 32;
    int m0   = blockIdx.x * GBM;
    int n0   = blockIdx.y * GBN;

    float acc[2][4][4];
#pragma unroll
    for (int i = 0; i < 2; i++)
#pragma unroll
        for (int j = 0; j < 4; j++)
#pragma unroll
            for (int r = 0; r < 4; r++) acc[i][j][r] = 0.f;

    for (int k0 = 0; k0 < K; k0 += GBK) {
#pragma unroll
        for (int i = 0; i < 2; i++) {
            int id = tid + 256 * i;
            int q  = id >> 7;
            int r  = id & 127;
            int gr = m0 + r;
            float4 v = make_float4(0.f, 0.f, 0.f, 0.f);
            if (gr < M) v = *(const float4*)(A + (size_t)gr * K + k0 + q * 4);
            float e[4] = {v.x, v.y, v.z, v.w};
#pragma unroll
            for (int t = 0; t < 4; t++) {
                int k = q * 4 + t;
                unsigned hb = f2tf(e[t]);
                float hf = __uint_as_float(hb);
                Ah[k][r] = hf;
                Al[k][r] = __uint_as_float(f2tf(e[t] - hf));
            }
        }
        {
            int kk = tid >> 4;
            int nq = tid & 15;
            float4 v = *(const float4*)(B + (size_t)(k0 + kk) * N + n0 + nq * 4);
            float e[4] = {v.x, v.y, v.z, v.w};
            float hi[4], lo[4];
#pragma unroll
            for (int t = 0; t < 4; t++) {
                unsigned hb = f2tf(e[t]);
                hi[t] = __uint_as_float(hb);
                lo[t] = __uint_as_float(f2tf(e[t] - hi[t]));
            }
            *(float4*)&Bh[kk][nq * 4] = make_float4(hi[0], hi[1], hi[2], hi[3]);
            *(float4*)&Bl[kk][nq * 4] = make_float4(lo[0], lo[1], lo[2], lo[3]);
        }
        __syncthreads();

#pragma unroll
        for (int ks = 0; ks < GBK; ks += 8) {
            unsigned ah[2][4], bh[4][2], tmp[2][4];
#pragma unroll
            for (int i = 0; i < 2; i++) {
                int rb = wm + i * 16;
                ah[i][0] = __float_as_uint(Ah[ks + tig    ][rb + g    ]);
                ah[i][1] = __float_as_uint(Ah[ks + tig    ][rb + g + 8]);
                ah[i][2] = __float_as_uint(Ah[ks + tig + 4][rb + g    ]);
                ah[i][3] = __float_as_uint(Ah[ks + tig + 4][rb + g + 8]);
            }
#pragma unroll
            for (int j = 0; j < 4; j++) {
                int nb = wn + j * 8;
                bh[j][0] = __float_as_uint(Bh[ks + tig    ][nb + g]);
                bh[j][1] = __float_as_uint(Bh[ks + tig + 4][nb + g]);
            }
#pragma unroll
            for (int i = 0; i < 2; i++)
#pragma unroll
                for (int j = 0; j < 4; j++) mma_tf32(acc[i][j], ah[i], bh[j]);
#pragma unroll
            for (int i = 0; i < 2; i++) {
                int rb = wm + i * 16;
                tmp[i][0] = __float_as_uint(Al[ks + tig    ][rb + g    ]);
                tmp[i][1] = __float_as_uint(Al[ks + tig    ][rb + g + 8]);
                tmp[i][2] = __float_as_uint(Al[ks + tig + 4][rb + g    ]);
                tmp[i][3] = __float_as_uint(Al[ks + tig + 4][rb + g + 8]);
            }
#pragma unroll
            for (int i = 0; i < 2; i++)
#pragma unroll
                for (int j = 0; j < 4; j++) mma_tf32(acc[i][j], tmp[i], bh[j]);
            unsigned bl[4][2];
#pragma unroll
            for (int j = 0; j < 4; j++) {
                int nb = wn + j * 8;
                bl[j][0] = __float_as_uint(Bl[ks + tig    ][nb + g]);
                bl[j][1] = __float_as_uint(Bl[ks + tig + 4][nb + g]);
            }
#pragma unroll
            for (int i = 0; i < 2; i++)
#pragma unroll
                for (int j = 0; j < 4; j++) mma_tf32(acc[i][j], ah[i], bl[j]);
        }
        __syncthreads();
    }

    // epilogue: store C
#pragma unroll
    for (int i = 0; i < 2; i++) {
#pragma unroll
        for (int j = 0; j < 4; j++) {
            int row = m0 + wm + i * 16 + g;
            int col = n0 + wn + j * 8 + 2 * tig;
            if (row < M)
                *(float2*)(C + (size_t)row * N + col) =
                    make_float2(acc[i][j][0], acc[i][j][1]);
            if (row + 8 < M)
                *(float2*)(C + (size_t)(row + 8) * N + col) =
                    make_float2(acc[i][j][2], acc[i][j][3]);
        }
    }

    // fused per-head attention dots (layer 1: N==64, one y-block, head = 8 cols)
    if (fuse) {
#pragma unroll
        for (int i = 0; i < 2; i++) {
            int r0 = m0 + wm + i * 16 + g;
#pragma unroll
            for (int j = 0; j < 4; j++) {
                int col = wn + j * 8 + 2 * tig;
                float s0 = acc[i][j][0] * asv[col] + acc[i][j][1] * asv[col + 1];
                float d0 = acc[i][j][0] * adv[col] + acc[i][j][1] * adv[col + 1];
                float s1 = acc[i][j][2] * asv[col] + acc[i][j][3] * asv[col + 1];
                float d1 = acc[i][j][2] * adv[col] + acc[i][j][3] * adv[col + 1];
#pragma unroll
                for (int off = 1; off < 4; off <<= 1) {
                    s0 += __shfl_xor_sync(0xffffffffu, s0, off);
                    d0 += __shfl_xor_sync(0xffffffffu, d0, off);
                    s1 += __shfl_xor_sync(0xffffffffu, s1, off);
                    d1 += __shfl_xor_sync(0xffffffffu, d1, off);
                }
                if (tig == 0) {
                    int h = (wn >> 3) + j;
                    if (r0 < M)     { sout[r0 * NHEADS + h] = s0;
                                      dout[r0 * NHEADS + h] = d0; }
                    if (r0 + 8 < M) { sout[(r0 + 8) * NHEADS + h] = s1;
                                      dout[(r0 + 8) * NHEADS + h] = d1; }
                }
            }
        }
    }
}

// ------------------ CSR build ------------------------------------------------
__global__ void count_kernel(const int* __restrict__ dst, int ne, int n)
{
    int i = blockIdx.x * blockDim.x + threadIdx.x;
    if (i >= ne + n) return;
    int d = (i < ne) ? dst[i] : (i - ne);
    atomicAdd(&g_deg[d], 1);
}

// multi-block scan: stage 1 — per-block (4096 elems) local exclusive scan
__global__ void __launch_bounds__(1024) scan1_kernel(int n)
{
    __shared__ int warpsums[32];
    int tid = threadIdx.x, lane = tid & 31, wid = tid >> 5;
    int i0 = blockIdx.x * 4096 + tid * 4;
    int v[4];
#pragma unroll
    for (int k = 0; k < 4; k++) {
        int i = i0 + k;
        v[k] = (i < n) ? g_deg[i] : 0;
    }
    int tsum = v[0] + v[1] + v[2] + v[3];
    int x = tsum;
#pragma unroll
    for (int off = 1; off < 32; off <<= 1) {
        int t = __shfl_up_sync(0xffffffffu, x, off);
        if (lane >= off) x += t;
    }
    if (lane == 31) warpsums[wid] = x;
    __syncthreads();
    if (wid == 0) {
        int wv = warpsums[lane];
#pragma unroll
        for (int off = 1; off < 32; off <<= 1) {
            int t = __shfl_up_sync(0xffffffffu, wv, off);
            if (lane >= off) wv += t;
        }
        warpsums[lane] = wv;
    }
    __syncthreads();
    int warp_off = (wid > 0) ? warpsums[wid - 1] : 0;
    int run = warp_off + (x - tsum);
#pragma unroll
    for (int k = 0; k < 4; k++) {
        int i = i0 + k;
        if (i < n) g_rowptr[i] = run;
        run += v[k];
    }
    if (tid == 1023) g_blocksum[blockIdx.x] = warp_off + x;
}

// stage 2 — scan the (<=16) block sums, write grand total to rowptr[n]
__global__ void scan2_kernel(int nb, int n)
{
    int lane = threadIdx.x;
    int v = (lane < nb) ? g_blocksum[lane] : 0;
    int x = v;
#pragma unroll
    for (int off = 1; off < 32; off <<= 1) {
        int t = __shfl_up_sync(0xffffffffu, x, off);
        if (lane >= off) x += t;
    }
    if (lane < nb) g_blockoff[lane] = x - v;
    if (lane == 31) g_rowptr[n] = x;
}

// stage 3 — add block offsets, fill cursor array
__global__ void scan3_kernel(int n)
{
    int i = blockIdx.x * blockDim.x + threadIdx.x;
    if (i >= n) return;
    int r = g_rowptr[i] + g_blockoff[i >> 12];
    g_rowptr[i] = r;
    g_cur[i]    = r;
}

__global__ void scatter_kernel(const int* __restrict__ src,
                               const int* __restrict__ dst, int ne, int n)
{
    int i = blockIdx.x * blockDim.x + threadIdx.x;
    if (i >= ne + n) return;
    int s, d;
    if (i < ne) { s = src[i]; d = dst[i]; }
    else        { s = d = i - ne; }
    int pos = atomicAdd(&g_cur[d], 1);
    g_csrc[pos] = s;
}

// ------------------ layer-1 gather (4-wide unrolled) -------------------------
__global__ void __launch_bounds__(256) gather1_kernel(const float* __restrict__ bias, int n)
{
    int gw   = (blockIdx.x * blockDim.x + threadIdx.x) >> 5;
    int lane = threadIdx.x & 31;
    if (gw >= n) return;
    int h = lane >> 2;
    float dv = g_d1[gw * NHEADS + h];
    int j0 = g_rowptr[gw], j1 = g_rowptr[gw + 1];
    float acc0 = 0.f, acc1 = 0.f, den = 0.f;
    int j = j0;
    for (; j + 3 < j1; j += 4) {
        int s0 = g_csrc[j], s1 = g_csrc[j + 1], s2 = g_csrc[j + 2], s3 = g_csrc[j + 3];
        float a0 = g_s1[s0 * NHEADS + h] + dv;
        float a1 = g_s1[s1 * NHEADS + h] + dv;
        float a2 = g_s1[s2 * NHEADS + h] + dv;
        float a3 = g_s1[s3 * NHEADS + h] + dv;
        float2 h0 = *(const float2*)(g_h1 + s0 * H1DIM + lane * 2);
        float2 h1 = *(const float2*)(g_h1 + s1 * H1DIM + lane * 2);
        float2 h2 = *(const float2*)(g_h1 + s2 * H1DIM + lane * 2);
        float2 h3 = *(const float2*)(g_h1 + s3 * H1DIM + lane * 2);
        a0 = (a0 > 0.f) ? a0 : 0.2f * a0;  float e0 = __expf(a0);
        a1 = (a1 > 0.f) ? a1 : 0.2f * a1;  float e1 = __expf(a1);
        a2 = (a2 > 0.f) ? a2 : 0.2f * a2;  float e2 = __expf(a2);
        a3 = (a3 > 0.f) ? a3 : 0.2f * a3;  float e3 = __expf(a3);
        den += (e0 + e1) + (e2 + e3);
        acc0 = fmaf(e0, h0.x, acc0); acc1 = fmaf(e0, h0.y, acc1);
        acc0 = fmaf(e1, h1.x, acc0); acc1 = fmaf(e1, h1.y, acc1);
        acc0 = fmaf(e2, h2.x, acc0); acc1 = fmaf(e2, h2.y, acc1);
        acc0 = fmaf(e3, h3.x, acc0); acc1 = fmaf(e3, h3.y, acc1);
    }
    for (; j < j1; j++) {
        int s = g_csrc[j];
        float a = g_s1[s * NHEADS + h] + dv;
        a = (a > 0.f) ? a : 0.2f * a;
        float ea = __expf(a);
        den += ea;
        float2 hv = *(const float2*)(g_h1 + s * H1DIM + lane * 2);
        acc0 = fmaf(ea, hv.x, acc0);
        acc1 = fmaf(ea, hv.y, acc1);
    }
    float inv = 1.f / den;
    int c = lane * 2;
    float v0 = acc0 * inv + bias[c];
    float v1 = acc1 * inv + bias[c + 1];
    v0 = (v0 > 0.f) ? v0 : expm1f(v0);
    v1 = (v1 > 0.f) ? v1 : expm1f(v1);
    *(float2*)(g_h1b + gw * H1DIM + c) = make_float2(v0, v1);
}

// ------------------ layer-2 per-node attention coefficients ------------------
__global__ void sd2_kernel(const float* __restrict__ att_src,
                           const float* __restrict__ att_dst, int n)
{
    int gt   = blockIdx.x * blockDim.x + threadIdx.x;
    int node = gt >> 5;
    int lane = gt & 31;
    if (node >= n) return;
    float4 hv = *(const float4*)(g_h2 + (size_t)node * OUT_CH + lane * 4);
    float4 as = *(const float4*)(att_src + lane * 4);
    float4 ad = *(const float4*)(att_dst + lane * 4);
    float s = hv.x * as.x + hv.y * as.y + hv.z * as.z + hv.w * as.w;
    float d = hv.x * ad.x + hv.y * ad.y + hv.z * ad.z + hv.w * ad.w;
#pragma unroll
    for (int off = 16; off > 0; off >>= 1) {
        s += __shfl_down_sync(0xffffffffu, s, off);
        d += __shfl_down_sync(0xffffffffu, d, off);
    }
    if (lane == 0) { g_s2[node] = s; g_d2[node] = d; }
}

// ------------------ layer-2 gather (4-wide unrolled) -> final output ---------
__global__ void __launch_bounds__(256) gather2_kernel(const float* __restrict__ bias,
                                                      float* __restrict__ out, int n)
{
    int gw   = (blockIdx.x * blockDim.x + threadIdx.x) >> 5;
    int lane = threadIdx.x & 31;
    if (gw >= n) return;
    float dv = g_d2[gw];
    int j0 = g_rowptr[gw], j1 = g_rowptr[gw + 1];
    float a0 = 0.f, a1 = 0.f, a2 = 0.f, a3 = 0.f, den = 0.f;
    int j = j0;
    for (; j + 3 < j1; j += 4) {
        int s0 = g_csrc[j], s1 = g_csrc[j + 1], s2 = g_csrc[j + 2], s3 = g_csrc[j + 3];
        float x0 = g_s2[s0] + dv, x1 = g_s2[s1] + dv;
        float x2 = g_s2[s2] + dv, x3 = g_s2[s3] + dv;
        float4 h0 = *(const float4*)(g_h2 + (size_t)s0 * OUT_CH + lane * 4);
        float4 h1 = *(const float4*)(g_h2 + (size_t)s1 * OUT_CH + lane * 4);
        float4 h2 = *(const float4*)(g_h2 + (size_t)s2 * OUT_CH + lane * 4);
        float4 h3 = *(const float4*)(g_h2 + (size_t)s3 * OUT_CH + lane * 4);
        x0 = (x0 > 0.f) ? x0 : 0.2f * x0;  float e0 = __expf(x0);
        x1 = (x1 > 0.f) ? x1 : 0.2f * x1;  float e1 = __expf(x1);
        x2 = (x2 > 0.f) ? x2 : 0.2f * x2;  float e2 = __expf(x2);
        x3 = (x3 > 0.f) ? x3 : 0.2f * x3;  float e3 = __expf(x3);
        den += (e0 + e1) + (e2 + e3);
        a0 = fmaf(e0, h0.x, a0); a1 = fmaf(e0, h0.y, a1);
        a2 = fmaf(e0, h0.z, a2); a3 = fmaf(e0, h0.w, a3);
        a0 = fmaf(e1, h1.x, a0); a1 = fmaf(e1, h1.y, a1);
        a2 = fmaf(e1, h1.z, a2); a3 = fmaf(e1, h1.w, a3);
        a0 = fmaf(e2, h2.x, a0); a1 = fmaf(e2, h2.y, a1);
        a2 = fmaf(e2, h2.z, a2); a3 = fmaf(e2, h2.w, a3);
        a0 = fmaf(e3, h3.x, a0); a1 = fmaf(e3, h3.y, a1);
        a2 = fmaf(e3, h3.z, a2); a3 = fmaf(e3, h3.w, a3);
    }
    for (; j < j1; j++) {
        int s = g_csrc[j];
        float x = g_s2[s] + dv;
        x = (x > 0.f) ? x : 0.2f * x;
        float ea = __expf(x);
        den += ea;
        float4 hv = *(const float4*)(g_h2 + (size_t)s * OUT_CH + lane * 4);
        a0 = fmaf(ea, hv.x, a0);
        a1 = fmaf(ea, hv.y, a1);
        a2 = fmaf(ea, hv.z, a2);
        a3 = fmaf(ea, hv.w, a3);
    }
    float inv = 1.f / den;
    int c = lane * 4;
    float v0 = a0 * inv + bias[c + 0];
    float v1 = a1 * inv + bias[c + 1];
    float v2 = a2 * inv + bias[c + 2];
    float v3 = a3 * inv + bias[c + 3];
    v0 = (v0 > 0.f) ? v0 : expm1f(v0);
    v1 = (v1 > 0.f) ? v1 : expm1f(v1);
    v2 = (v2 > 0.f) ? v2 : expm1f(v2);
    v3 = (v3 > 0.f) ? v3 : expm1f(v3);
    *(float4*)(out + (size_t)gw * OUT_CH + c) = make_float4(v0, v1, v2, v3);
}

// ------------------ launch ---------------------------------------------------
extern "C" void kernel_launch(void* const* d_in, const int* in_sizes, int n_in,
                              void* d_out, int out_size)
{
    const float* x   = (const float*)d_in[0];
    const int*   ei  = (const int*)  d_in[1];
    const float* W1  = (const float*)d_in[2];
    const float* as1 = (const float*)d_in[3];
    const float* ad1 = (const float*)d_in[4];
    const float* b1  = (const float*)d_in[5];
    const float* W2  = (const float*)d_in[6];
    const float* as2 = (const float*)d_in[7];
    const float* ad2 = (const float*)d_in[8];
    const float* b2  = (const float*)d_in[9];
    float* out = (float*)d_out;

    int n = in_sizes[0] / IN_CH;
    int e = in_sizes[1] / 2;
    const int* src = ei;
    const int* dst = ei + e;

    void *p_h1, *p_h1b, *p_h2, *p_s1, *p_d1, *p;
    cudaGetSymbolAddress(&p_h1,  g_h1);
    cudaGetSymbolAddress(&p_h1b, g_h1b);
    cudaGetSymbolAddress(&p_h2,  g_h2);
    cudaGetSymbolAddress(&p_s1,  g_s1);
    cudaGetSymbolAddress(&p_d1,  g_d1);

    // ---- CSR build (shared by both layers) ----
    cudaGetSymbolAddress(&p, g_deg);
    cudaMemsetAsync(p, 0, (size_t)n * 4);
    count_kernel<<<(e + n + 255) / 256, 256>>>(dst, e, n);
    int nb = (n + 4095) / 4096;
    scan1_kernel<<<nb, 1024>>>(n);
    scan2_kernel<<<1, 32>>>(nb, n);
    scan3_kernel<<<(n + 255) / 256, 256>>>(n);
    scatter_kernel<<<(e + n + 255) / 256, 256>>>(src, dst, e, n);

    // ---- layer 1 (GEMM with fused attention dots) ----
    {
        dim3 grid((n + GBM - 1) / GBM, H1DIM / GBN);
        gemm_tf32<<<grid, 256>>>(x, W1, (float*)p_h1, n, H1DIM, IN_CH,
                                 as1, ad1, (float*)p_s1, (float*)p_d1, 1);
    }
    gather1_kernel<<<(n * 32 + 255) / 256, 256>>>(b1, n);

    // ---- layer 2 ----
    {
        dim3 grid((n + GBM - 1) / GBM, OUT_CH / GBN);
        gemm_tf32<<<grid, 256>>>((const float*)p_h1b, W2, (float*)p_h2, n, OUT_CH, H1DIM,
                                 as2, ad2, nullptr, nullptr, 0);
    }
    sd2_kernel<<<(n * 32 + 255) / 256, 256>>>(as2, ad2, n);
    gather2_kernel<<<(n * 32 + 255) / 256, 256>>>(b2, out, n);
}